// round 11
// baseline (speedup 1.0000x reference)
#include <cuda_runtime.h>
#include <cuda_fp16.h>
#include <cstdint>

#define NMAX 100000
#define EMAX 1600000
#define HID 128

// ---------------- scratch (device globals; no allocations allowed) ----------
__device__ uint32_t g_xgh  [(size_t)NMAX * 64];   // xg fp16, plain layout
__device__ uint32_t g_diffh[(size_t)NMAX * 64];   // diffused fp16, k-permuted
__device__ uint32_t g_evh  [(size_t)NMAX * 32];   // ev fp16, k-permuted
__device__ uint32_t g_baseh[(size_t)NMAX * 64];   // base fp16, k-permuted
__device__ int   g_deg[NMAX];
__device__ float g_dis[NMAX];
__device__ int   g_rowstart[NMAX];
__device__ int   g_cursor[NMAX];
__device__ int   g_csr[EMAX];
// fp16 transposed + k-permuted weights [128 n][K k]
__device__ __half g_wt_proj[128 * 64];
__device__ __half g_wt_gcn [128 * 128];
__device__ __half g_wt_gate[128 * 256];
__device__ __half g_wt_fuse[128 * 256];

// ---------------- PTX helpers --------------------------------------------------
__device__ __forceinline__ uint32_t smem_u32(const void* p) {
    uint32_t a;
    asm("{ .reg .u64 t; cvta.to.shared.u64 t, %1; cvt.u32.u64 %0, t; }" : "=r"(a) : "l"(p));
    return a;
}
__device__ __forceinline__ void cp16(uint32_t dst, const void* src) {
    asm volatile("cp.async.cg.shared.global [%0], [%1], 16;" :: "r"(dst), "l"(src));
}
__device__ __forceinline__ void cp_commit() {
    asm volatile("cp.async.commit_group;" ::: "memory");
}
template<int N>
__device__ __forceinline__ void cp_wait() {
    asm volatile("cp.async.wait_group %0;" :: "n"(N) : "memory");
}
__device__ __forceinline__ void mma_f16(float* c, uint32_t a0, uint32_t a1,
                                        uint32_t a2, uint32_t a3,
                                        uint32_t b0, uint32_t b1) {
    asm volatile(
        "mma.sync.aligned.m16n8k16.row.col.f32.f16.f16.f32 "
        "{%0,%1,%2,%3}, {%4,%5,%6,%7}, {%8,%9}, {%0,%1,%2,%3};"
        : "+f"(c[0]), "+f"(c[1]), "+f"(c[2]), "+f"(c[3])
        : "r"(a0), "r"(a1), "r"(a2), "r"(a3), "r"(b0), "r"(b1));
}

// k-word permutation within each 8-word group: pairs (w, w+4) become adjacent
__device__ __forceinline__ int perm8(int w) { return (w < 4) ? 2 * w : 2 * (w - 4) + 1; }
__device__ __forceinline__ int permw(int w) { return ((w >> 3) << 3) + perm8(w & 7); }

// smem geometry (uint32 words)
#define LDR   72
#define EF_W  (128 * LDR)      // 9216: one resident 128x128-half tile
#define SUB_W 1024             // one 8-word-per-row sub-tile
#define CH_W  2048             // one stage = K=32 slice = 2 sub-tiles
// k_proj_gcn:  ef | 2 A stages | 2 B stages | bias
#define PG_SMEM_W (EF_W + 2 * CH_W + 2 * CH_W + 128)
// k_gate_fuse: corr | baseR | 2 A stages | 2 B stages | 2 biases
#define GF_SMEM_W (2 * EF_W + 2 * CH_W + 2 * CH_W + 256)

// ---------------- weight prep: half Wt[n][permk(k)] = W[k][n] -------------------
__global__ void wprep(const float* __restrict__ W0, const float* __restrict__ W1,
                      const float* __restrict__ W2, const float* __restrict__ W3,
                      __half* __restrict__ T0, __half* __restrict__ T1,
                      __half* __restrict__ T2, __half* __restrict__ T3)
{
    __shared__ float s[32][33];
    int b = blockIdx.x;
    const float* W; __half* T; int K;
    if (b < 8)       { W = W0; T = T0; K = 64;  }
    else if (b < 24) { W = W1; T = T1; K = 128; b -= 8;  }
    else if (b < 56) { W = W2; T = T2; K = 256; b -= 24; }
    else             { W = W3; T = T3; K = 256; b -= 56; }
    const int k0 = (b >> 2) * 32, n0 = (b & 3) * 32;
    const int tx = threadIdx.x & 31, ty = threadIdx.x >> 5;
#pragma unroll
    for (int i = 0; i < 4; i++)
        s[ty + i * 8][tx] = W[(size_t)(k0 + ty + i * 8) * HID + n0 + tx];
    __syncthreads();
    const int k = k0 + tx;
    const int col = ((k >> 4) << 4) + (perm8((k & 15) >> 1) << 1) + (k & 1);
#pragma unroll
    for (int i = 0; i < 4; i++) {
        const int n = n0 + ty + i * 8;
        T[(size_t)n * K + col] = __float2half(s[tx][ty + i * 8]);
    }
}

// ---------------- activation convert: fp32 -> k-permuted fp16 -------------------
template<int WPR>
__global__ void cvt_half(const float2* __restrict__ in, uint32_t* __restrict__ out,
                         int total_words)
{
    int idx = blockIdx.x * blockDim.x + threadIdx.x;
    if (idx >= total_words) return;
    const int row = idx / WPR, w = idx % WPR;
    const float2 v = in[idx];
    const __half2 h = __floats2half2_rn(v.x, v.y);
    out[(size_t)row * WPR + permw(w)] = *(const uint32_t*)&h;
}

// ================================================================================
// Fused kernel 1: ef = relu(evh @ Wp + bp) [fp16 smem-resident]; xg = ef @ Wgcn
// BK=32 chunks, 2-stage cp.async pipeline.
// ================================================================================
__global__ void __launch_bounds__(256, 2)
k_proj_gcn(const uint32_t* __restrict__ evh, const __half* __restrict__ Wtp,
           const float* __restrict__ bp, const __half* __restrict__ Wtg,
           uint32_t* __restrict__ xgh, int M)
{
    extern __shared__ uint32_t dsm[];
    uint32_t* ef = dsm;
    uint32_t* As = dsm + EF_W;
    uint32_t* Bs = As + 2 * CH_W;
    float*    sb = (float*)(Bs + 2 * CH_W);

    const int tid   = threadIdx.x;
    const int wid   = tid >> 5, lane = tid & 31;
    const int warpM = wid & 3,  warpN = wid >> 2;
    const int lr    = lane >> 2, lc = lane & 3;
    const int m0    = blockIdx.x * 128;

    if (tid < 128) sb[tid] = bp[tid];

    const uint32_t as_b = smem_u32(As);
    const uint32_t bs_b = smem_u32(Bs);

    float c[2][8][4];
#pragma unroll
    for (int mi = 0; mi < 2; mi++)
#pragma unroll
        for (int ni = 0; ni < 8; ni++)
#pragma unroll
            for (int j = 0; j < 4; j++) c[mi][ni][j] = 0.f;

    const int r = tid >> 1, q = tid & 1;
    int gr = m0 + r; if (gr > M - 1) gr = M - 1;

    // K=32 chunk copies (2 sub-tiles per stage)
    auto issueA = [&](int st, int ch) {
#pragma unroll
        for (int sub = 0; sub < 2; sub++)
            cp16(as_b + (uint32_t)(st * CH_W + sub * SUB_W + r * 8 + q * 4) * 4,
                 evh + (size_t)gr * 32 + ch * 16 + sub * 8 + q * 4);
    };
    auto issueB = [&](int st, int ch, const __half* Wt, int K) {
#pragma unroll
        for (int sub = 0; sub < 2; sub++)
            cp16(bs_b + (uint32_t)(st * CH_W + sub * SUB_W + r * 8 + q * 4) * 4,
                 Wt + (size_t)r * K + ch * 32 + sub * 16 + q * 8);
    };
    auto compute = [&](const uint32_t* Ab, int lda, int wb, const uint32_t* Bb) {
        uint32_t a0[2], a1[2], a2[2], a3[2];
#pragma unroll
        for (int mi = 0; mi < 2; mi++) {
            const int row = warpM * 32 + mi * 16 + lr;
            const uint2 lo = *(const uint2*)(Ab + row * lda + wb + 2 * lc);
            const uint2 hi = *(const uint2*)(Ab + (row + 8) * lda + wb + 2 * lc);
            a0[mi] = lo.x; a1[mi] = hi.x; a2[mi] = lo.y; a3[mi] = hi.y;
        }
#pragma unroll
        for (int ni = 0; ni < 8; ni++) {
            const uint2 bb = *(const uint2*)(Bb + (warpN * 64 + ni * 8 + lr) * 8 + 2 * lc);
#pragma unroll
            for (int mi = 0; mi < 2; mi++)
                mma_f16(c[mi][ni], a0[mi], a1[mi], a2[mi], a3[mi], bb.x, bb.y);
        }
    };

    // ---- phase 1: K=64 -> 2 chunks of K=32
    issueA(0, 0); issueB(0, 0, Wtp, 64); cp_commit();
    for (int i = 0; i < 2; i++) {
        cp_wait<0>();
        __syncthreads();
        if (i == 0) { issueA(1, 1); issueB(1, 1, Wtp, 64); cp_commit(); }
        else        { issueB(0, 0, Wtg, 128); cp_commit(); }   // prefetch phase-2 B0
        const uint32_t* Ast = As + (i & 1) * CH_W;
        const uint32_t* Bst = Bs + (i & 1) * CH_W;
        compute(Ast, 8, 0, Bst);
        compute(Ast + SUB_W, 8, 0, Bst + SUB_W);
    }

    // ---- epilogue 1: relu(v+b) -> permuted fp16 into ef
#pragma unroll
    for (int mi = 0; mi < 2; mi++)
#pragma unroll
        for (int half = 0; half < 2; half++) {
            const int row = warpM * 32 + mi * 16 + lr + half * 8;
#pragma unroll
            for (int ni = 0; ni < 8; ni++) {
                const int col = warpN * 64 + ni * 8 + lc * 2;
                const float v0 = fmaxf(c[mi][ni][half * 2 + 0] + sb[col + 0], 0.f);
                const float v1 = fmaxf(c[mi][ni][half * 2 + 1] + sb[col + 1], 0.f);
                const __half2 h = __floats2half2_rn(v0, v1);
                ef[row * LDR + permw(col >> 1)] = *(const uint32_t*)&h;
            }
        }

#pragma unroll
    for (int mi = 0; mi < 2; mi++)
#pragma unroll
        for (int ni = 0; ni < 8; ni++)
#pragma unroll
            for (int j = 0; j < 4; j++) c[mi][ni][j] = 0.f;

    // ---- phase 2: xg = ef @ Wgcn, K=128 -> 4 chunks, A resident
    for (int i = 0; i < 4; i++) {
        cp_wait<0>();
        __syncthreads();                     // also orders epilogue-1 ef writes at i=0
        if (i + 1 < 4) { issueB((i + 1) & 1, i + 1, Wtg, 128); cp_commit(); }
        const uint32_t* Bst = Bs + (i & 1) * CH_W;
        compute(ef, LDR, i * 16, Bst);
        compute(ef, LDR, i * 16 + 8, Bst + SUB_W);
    }

    // ---- epilogue 2: xg fp16 plain layout
#pragma unroll
    for (int mi = 0; mi < 2; mi++)
#pragma unroll
        for (int half = 0; half < 2; half++) {
            const int row = m0 + warpM * 32 + mi * 16 + lr + half * 8;
            if (row >= M) continue;
#pragma unroll
            for (int ni = 0; ni < 8; ni++) {
                const int col = warpN * 64 + ni * 8 + lc * 2;
                const __half2 h = __floats2half2_rn(c[mi][ni][half * 2 + 0],
                                                    c[mi][ni][half * 2 + 1]);
                xgh[(size_t)row * 64 + (col >> 1)] = *(const uint32_t*)&h;
            }
        }
}

// ================================================================================
// Fused kernel 2: gate GEMM -> corrected (smem) -> fuse GEMM. BK=32, 2 stages.
// ================================================================================
__global__ void __launch_bounds__(256, 2)
k_gate_fuse(const uint32_t* __restrict__ baseh, const uint32_t* __restrict__ diffh,
            const __half* __restrict__ Wtg, const float* __restrict__ bg,
            const __half* __restrict__ Wtf, const float* __restrict__ bf,
            float* __restrict__ out, int M)
{
    extern __shared__ uint32_t dsm[];
    uint32_t* corr  = dsm;
    uint32_t* baseR = dsm + EF_W;
    uint32_t* As    = baseR + EF_W;
    uint32_t* Bs    = As + 2 * CH_W;
    float*    sbg   = (float*)(Bs + 2 * CH_W);
    float*    sbf   = sbg + 128;

    const int tid   = threadIdx.x;
    const int wid   = tid >> 5, lane = tid & 31;
    const int warpM = wid & 3,  warpN = wid >> 2;
    const int lr    = lane >> 2, lc = lane & 3;
    const int m0    = blockIdx.x * 128;

    if (tid < 128) { sbg[tid] = bg[tid]; sbf[tid] = bf[tid]; }

    const uint32_t br_b = smem_u32(baseR);
    const uint32_t as_b = smem_u32(As);
    const uint32_t bs_b = smem_u32(Bs);

    const int r = tid >> 1, q = tid & 1;
    int gr = m0 + r; if (gr > M - 1) gr = M - 1;

    float c[2][8][4];
#pragma unroll
    for (int mi = 0; mi < 2; mi++)
#pragma unroll
        for (int ni = 0; ni < 8; ni++)
#pragma unroll
            for (int j = 0; j < 4; j++) c[mi][ni][j] = 0.f;

    auto issueA = [&](int ch) {          // diff streamed, gate chunks 4..7
#pragma unroll
        for (int sub = 0; sub < 2; sub++)
            cp16(as_b + (uint32_t)((ch & 1) * CH_W + sub * SUB_W + r * 8 + q * 4) * 4,
                 diffh + (size_t)gr * 64 + (ch - 4) * 16 + sub * 8 + q * 4);
    };
    auto issueB = [&](int ch, const __half* Wt) {
#pragma unroll
        for (int sub = 0; sub < 2; sub++)
            cp16(bs_b + (uint32_t)((ch & 1) * CH_W + sub * SUB_W + r * 8 + q * 4) * 4,
                 Wt + (size_t)r * 256 + ch * 32 + sub * 16 + q * 8);
    };
    auto compute = [&](const uint32_t* Ab, int lda, int wb, const uint32_t* Bb) {
        uint32_t a0[2], a1[2], a2[2], a3[2];
#pragma unroll
        for (int mi = 0; mi < 2; mi++) {
            const int row = warpM * 32 + mi * 16 + lr;
            const uint2 lo = *(const uint2*)(Ab + row * lda + wb + 2 * lc);
            const uint2 hi = *(const uint2*)(Ab + (row + 8) * lda + wb + 2 * lc);
            a0[mi] = lo.x; a1[mi] = hi.x; a2[mi] = lo.y; a3[mi] = hi.y;
        }
#pragma unroll
        for (int ni = 0; ni < 8; ni++) {
            const uint2 bb = *(const uint2*)(Bb + (warpN * 64 + ni * 8 + lr) * 8 + 2 * lc);
#pragma unroll
            for (int mi = 0; mi < 2; mi++)
                mma_f16(c[mi][ni], a0[mi], a1[mi], a2[mi], a3[mi], bb.x, bb.y);
        }
    };

    // ---- load full baseR tile (group 0) + gate B chunk 0 (group 1)
#pragma unroll
    for (int c8 = 0; c8 < 8; c8++)
        cp16(br_b + (uint32_t)(r * LDR + c8 * 8 + q * 4) * 4,
             baseh + (size_t)gr * 64 + c8 * 8 + q * 4);
    cp_commit();
    issueB(0, Wtg); cp_commit();

    // ---- gate GEMM: K=256 -> 8 chunks of K=32
    for (int i = 0; i < 8; i++) {
        cp_wait<0>();
        __syncthreads();
        if (i + 1 < 8) {
            issueB(i + 1, Wtg);
            if (i + 1 >= 4) issueA(i + 1);
            cp_commit();
        }
        const uint32_t* Bst = Bs + (i & 1) * CH_W;
        if (i < 4) {
            compute(baseR, LDR, i * 16, Bst);
            compute(baseR, LDR, i * 16 + 8, Bst + SUB_W);
        } else {
            const uint32_t* Ast = As + (i & 1) * CH_W;
            compute(Ast, 8, 0, Bst);
            compute(Ast + SUB_W, 8, 0, Bst + SUB_W);
        }
    }

    // prefetch fuse B chunk 0 (stage 0; last used by gate chunk 6, safe)
    issueB(0, Wtf); cp_commit();

    // ---- gate epilogue: corrected -> permuted fp16 in smem
#pragma unroll
    for (int mi = 0; mi < 2; mi++)
#pragma unroll
        for (int half = 0; half < 2; half++) {
            const int lrow = warpM * 32 + mi * 16 + lr + half * 8;
            const int row  = m0 + lrow;
            const size_t rbase = (size_t)(row < M ? row : M - 1) * 64;
#pragma unroll
            for (int ni = 0; ni < 8; ni++) {
                const int col = warpN * 64 + ni * 8 + lc * 2;
                const int pw  = permw(col >> 1);
                const uint32_t ub = baseR[lrow * LDR + pw];
                const uint32_t ud = diffh[rbase + pw];
                const float2 b2 = __half22float2(*(const __half2*)&ub);
                const float2 d2 = __half22float2(*(const __half2*)&ud);
                const float g0 = 1.f / (1.f + __expf(-(c[mi][ni][half * 2 + 0] + sbg[col + 0])));
                const float g1 = 1.f / (1.f + __expf(-(c[mi][ni][half * 2 + 1] + sbg[col + 1])));
                const float v0 = fmaf(d2.x - b2.x, g0, b2.x);
                const float v1 = fmaf(d2.y - b2.y, g1, b2.y);
                const __half2 h = __floats2half2_rn(v0, v1);
                corr[lrow * LDR + pw] = *(const uint32_t*)&h;
            }
        }

#pragma unroll
    for (int mi = 0; mi < 2; mi++)
#pragma unroll
        for (int ni = 0; ni < 8; ni++)
#pragma unroll
            for (int j = 0; j < 4; j++) c[mi][ni][j] = 0.f;

    // ---- fuse GEMM: K=256 -> 8 chunks; A entirely smem-resident
    for (int i = 0; i < 8; i++) {
        cp_wait<0>();
        __syncthreads();                    // orders corr writes at i=0
        if (i + 1 < 8) { issueB(i + 1, Wtf); cp_commit(); }
        const uint32_t* Bst = Bs + (i & 1) * CH_W;
        if (i < 4) {
            compute(baseR, LDR, i * 16, Bst);
            compute(baseR, LDR, i * 16 + 8, Bst + SUB_W);
        } else {
            compute(corr, LDR, (i - 4) * 16, Bst);
            compute(corr, LDR, (i - 4) * 16 + 8, Bst + SUB_W);
        }
    }

    // ---- fuse epilogue: relu(v + bf) -> out (fp32)
#pragma unroll
    for (int mi = 0; mi < 2; mi++)
#pragma unroll
        for (int half = 0; half < 2; half++) {
            const int row = m0 + warpM * 32 + mi * 16 + lr + half * 8;
            if (row >= M) continue;
#pragma unroll
            for (int ni = 0; ni < 8; ni++) {
                const int col = warpN * 64 + ni * 8 + lc * 2;
                *(float2*)(out + (size_t)row * HID + col) =
                    make_float2(fmaxf(c[mi][ni][half * 2 + 0] + sbf[col + 0], 0.f),
                                fmaxf(c[mi][ni][half * 2 + 1] + sbf[col + 1], 0.f));
            }
        }
}

// ---------------- per-block edge-dtype detection --------------------------------
// int64 ids < 2^31 => all odd 32-bit words zero; int32 => some sampled word nonzero.
__device__ __forceinline__ int detect_is32(const void* ei) {
    const unsigned* p = (const unsigned*)ei;
    int any = 0;
    for (int i = threadIdx.x; i < 256; i += blockDim.x)
        any |= (p[2 * i + 1] != 0u);
    return __syncthreads_or(any);
}

// ---------------- degree / CSR ---------------------------------------------------
__global__ void count_deg(const void* __restrict__ ei, int E) {
    const int is32 = detect_is32(ei);
    int e = blockIdx.x * blockDim.x + threadIdx.x;
    if (e >= E) return;
    int d = is32 ? ((const int*)ei)[(size_t)E + e]
                 : (int)((const long long*)ei)[(size_t)E + e];
    atomicAdd(&g_deg[d], 1);
}

// single-block full scan: dis, rowstart, cursor in one launch
__global__ void __launch_bounds__(1024, 1) scan_all(int n) {
    __shared__ int ts[1024];
    const int per = (n + 1023) >> 10;
    const int start = threadIdx.x * per;
    const int end   = (start + per < n) ? start + per : n;
    int sum = 0;
    for (int i = start; i < end; i++) {
        const int d = g_deg[i];
        g_dis[i] = rsqrtf((float)(d + 1));
        sum += d;
    }
    ts[threadIdx.x] = sum;
    __syncthreads();
    for (int off = 1; off < 1024; off <<= 1) {
        int t = (threadIdx.x >= off) ? ts[threadIdx.x - off] : 0;
        __syncthreads();
        ts[threadIdx.x] += t;
        __syncthreads();
    }
    int run = ts[threadIdx.x] - sum;   // exclusive prefix
    for (int i = start; i < end; i++) {
        g_rowstart[i] = run;
        g_cursor[i]   = run;
        run += g_deg[i];
    }
}

__global__ void fill_csr(const void* __restrict__ ei, int E) {
    const int is32 = detect_is32(ei);
    int e = blockIdx.x * blockDim.x + threadIdx.x;
    if (e >= E) return;
    int s, d;
    if (is32) {
        s = ((const int*)ei)[e];
        d = ((const int*)ei)[(size_t)E + e];
    } else {
        s = (int)((const long long*)ei)[e];
        d = (int)((const long long*)ei)[(size_t)E + e];
    }
    int pos = atomicAdd(&g_cursor[d], 1);
    g_csr[pos] = s;
}

// ---------------- aggregation: warp per node, fp16 gather-sum --------------------
__device__ __forceinline__ float4 h4f(uint2 v) {
    const float2 f0 = __half22float2(*(const __half2*)&v.x);
    const float2 f1 = __half22float2(*(const __half2*)&v.y);
    return make_float4(f0.x, f0.y, f1.x, f1.y);
}
__global__ void aggregate(const float* __restrict__ b_gcn, int n) {
    int gw   = (blockIdx.x * blockDim.x + threadIdx.x) >> 5;
    int lane = threadIdx.x & 31;
    if (gw >= n) return;
    const int node = gw;
    const uint2* __restrict__ xg2 = (const uint2*)g_xgh;

    const float4 selfv = h4f(xg2[(size_t)node * 32 + lane]);
    const float  dn    = g_dis[node];
    const int    s0    = g_rowstart[node];
    const int    cnt   = g_deg[node];

    float4 acc = make_float4(0.f, 0.f, 0.f, 0.f);
    int e = s0, eend = s0 + cnt;
    for (; e + 1 < eend; e += 2) {
        const int s1 = g_csr[e], s2 = g_csr[e + 1];
        const float w1 = g_dis[s1], w2 = g_dis[s2];
        const float4 v1 = h4f(xg2[(size_t)s1 * 32 + lane]);
        const float4 v2 = h4f(xg2[(size_t)s2 * 32 + lane]);
        acc.x += v1.x * w1 + v2.x * w2;
        acc.y += v1.y * w1 + v2.y * w2;
        acc.z += v1.z * w1 + v2.z * w2;
        acc.w += v1.w * w1 + v2.w * w2;
    }
    if (e < eend) {
        const int s1 = g_csr[e];
        const float w1 = g_dis[s1];
        const float4 v1 = h4f(xg2[(size_t)s1 * 32 + lane]);
        acc.x += v1.x * w1; acc.y += v1.y * w1;
        acc.z += v1.z * w1; acc.w += v1.w * w1;
    }
    const float sw = dn * dn;
    const float4 b = ((const float4*)b_gcn)[lane];
    float4 o;
    o.x = fmaxf(acc.x * dn + selfv.x * sw + b.x, 0.f);
    o.y = fmaxf(acc.y * dn + selfv.y * sw + b.y, 0.f);
    o.z = fmaxf(acc.z * dn + selfv.z * sw + b.z, 0.f);
    o.w = fmaxf(acc.w * dn + selfv.w * sw + b.w, 0.f);
    const __half2 h0 = __floats2half2_rn(o.x, o.y);
    const __half2 h1 = __floats2half2_rn(o.z, o.w);
    uint32_t* drow = g_diffh + (size_t)node * 64;
    drow[permw(2 * lane)]     = *(const uint32_t*)&h0;
    drow[permw(2 * lane + 1)] = *(const uint32_t*)&h1;
}

// ---------------- launcher --------------------------------------------------------
extern "C" void kernel_launch(void* const* d_in, const int* in_sizes, int n_in,
                              void* d_out, int out_size)
{
    const float* base   = (const float*)d_in[0];
    const float* ev     = (const float*)d_in[1];
    const void*  ei     = d_in[2];
    const float* W_proj = (const float*)d_in[3];
    const float* b_proj = (const float*)d_in[4];
    const float* W_gcn  = (const float*)d_in[5];
    const float* b_gcn  = (const float*)d_in[6];
    const float* W_gate = (const float*)d_in[7];
    const float* b_gate = (const float*)d_in[8];
    const float* W_fuse = (const float*)d_in[9];
    const float* b_fuse = (const float*)d_in[10];

    const int N = in_sizes[0] / HID;
    const int E = in_sizes[2] / 2;

    uint32_t *p_xgh, *p_diffh, *p_evh, *p_baseh;
    __half *p_wtp, *p_wtg, *p_wtga, *p_wtf;
    int *p_deg;
    cudaGetSymbolAddress((void**)&p_xgh,   g_xgh);
    cudaGetSymbolAddress((void**)&p_diffh, g_diffh);
    cudaGetSymbolAddress((void**)&p_evh,   g_evh);
    cudaGetSymbolAddress((void**)&p_baseh, g_baseh);
    cudaGetSymbolAddress((void**)&p_wtp,   g_wt_proj);
    cudaGetSymbolAddress((void**)&p_wtg,   g_wt_gcn);
    cudaGetSymbolAddress((void**)&p_wtga,  g_wt_gate);
    cudaGetSymbolAddress((void**)&p_wtf,   g_wt_fuse);
    cudaGetSymbolAddress((void**)&p_deg,   g_deg);

    cudaFuncSetAttribute(k_proj_gcn,  cudaFuncAttributeMaxDynamicSharedMemorySize, PG_SMEM_W * 4);
    cudaFuncSetAttribute(k_gate_fuse, cudaFuncAttributeMaxDynamicSharedMemorySize, GF_SMEM_W * 4);

    const int gT = (N + 127) / 128;
    const int gE = (E + 255) / 256;

    // single side stream for CSR chain + base convert (destroyed before return)
    cudaStream_t side;
    cudaEvent_t evFork, evJoin;
    cudaStreamCreateWithFlags(&side, cudaStreamNonBlocking);
    cudaEventCreateWithFlags(&evFork, cudaEventDisableTiming);
    cudaEventCreateWithFlags(&evJoin, cudaEventDisableTiming);

    cudaEventRecord(evFork, 0);
    cudaStreamWaitEvent(side, evFork, 0);

    // --- side: CSR build + base convert
    cudaMemsetAsync(p_deg, 0, (size_t)N * sizeof(int), side);
    count_deg<<<gE, 256, 0, side>>>(ei, E);
    scan_all<<<1, 1024, 0, side>>>(N);
    fill_csr<<<gE, 256, 0, side>>>(ei, E);
    cvt_half<64><<<(N * 64 + 255) / 256, 256, 0, side>>>((const float2*)base, p_baseh, N * 64);
    cudaEventRecord(evJoin, side);

    // --- main: weight prep + ev convert + fused proj/gcn GEMM (overlaps side)
    wprep<<<88, 256>>>(W_proj, W_gcn, W_gate, W_fuse, p_wtp, p_wtg, p_wtga, p_wtf);
    cvt_half<32><<<(N * 32 + 255) / 256, 256>>>((const float2*)ev, p_evh, N * 32);
    k_proj_gcn<<<gT, 256, PG_SMEM_W * 4>>>(p_evh, p_wtp, b_proj, p_wtg, p_xgh, N);

    // join: aggregate needs xgh (main) + CSR (side); gate_fuse also needs baseh (side)
    cudaStreamWaitEvent(0, evJoin, 0);
    aggregate<<<(N * 32 + 255) / 256, 256>>>(b_gcn, N);

    k_gate_fuse<<<gT, 256, GF_SMEM_W * 4>>>(p_baseh, p_diffh, p_wtga, b_gate,
                                            p_wtf, b_fuse, (float*)d_out, N);

    // release resources created this call (graph retains captured dependencies)
    cudaEventDestroy(evFork);
    cudaEventDestroy(evJoin);
    cudaStreamDestroy(side);
}

// round 12
// speedup vs baseline: 1.7456x; 1.7456x over previous
#include <cuda_runtime.h>
#include <cuda_fp16.h>
#include <cstdint>

#define NMAX 100000
#define EMAX 1600000
#define HID 128

// ---------------- scratch (device globals; no allocations allowed) ----------
__device__ uint32_t g_xgh  [(size_t)NMAX * 64];   // xg fp16, plain layout
__device__ uint32_t g_diffh[(size_t)NMAX * 64];   // diffused fp16, k-permuted
__device__ uint32_t g_evh  [(size_t)NMAX * 32];   // ev fp16, k-permuted
__device__ uint32_t g_baseh[(size_t)NMAX * 64];   // base fp16, k-permuted
__device__ int   g_deg[NMAX];
__device__ float g_dis[NMAX];
__device__ int   g_rowstart[NMAX];
__device__ int   g_cursor[NMAX];
__device__ int   g_csr[EMAX];
__device__ int   g_bsum[1024];
// fp16 transposed + k-permuted weights [128 n][K k]
__device__ __half g_wt_proj[128 * 64];
__device__ __half g_wt_gcn [128 * 128];
__device__ __half g_wt_gate[128 * 256];
__device__ __half g_wt_fuse[128 * 256];

// ---------------- PTX helpers --------------------------------------------------
__device__ __forceinline__ uint32_t smem_u32(const void* p) {
    uint32_t a;
    asm("{ .reg .u64 t; cvta.to.shared.u64 t, %1; cvt.u32.u64 %0, t; }" : "=r"(a) : "l"(p));
    return a;
}
__device__ __forceinline__ void cp16(uint32_t dst, const void* src) {
    asm volatile("cp.async.cg.shared.global [%0], [%1], 16;" :: "r"(dst), "l"(src));
}
__device__ __forceinline__ void cp_commit() {
    asm volatile("cp.async.commit_group;" ::: "memory");
}
template<int N>
__device__ __forceinline__ void cp_wait() {
    asm volatile("cp.async.wait_group %0;" :: "n"(N) : "memory");
}
__device__ __forceinline__ void mma_f16(float* c, uint32_t a0, uint32_t a1,
                                        uint32_t a2, uint32_t a3,
                                        uint32_t b0, uint32_t b1) {
    asm volatile(
        "mma.sync.aligned.m16n8k16.row.col.f32.f16.f16.f32 "
        "{%0,%1,%2,%3}, {%4,%5,%6,%7}, {%8,%9}, {%0,%1,%2,%3};"
        : "+f"(c[0]), "+f"(c[1]), "+f"(c[2]), "+f"(c[3])
        : "r"(a0), "r"(a1), "r"(a2), "r"(a3), "r"(b0), "r"(b1));
}

// k-word permutation within each 8-word group: pairs (w, w+4) become adjacent
__device__ __forceinline__ int perm8(int w) { return (w < 4) ? 2 * w : 2 * (w - 4) + 1; }
__device__ __forceinline__ int permw(int w) { return ((w >> 3) << 3) + perm8(w & 7); }

// smem geometry (uint32 words)
#define LDR 72
#define EF_W   (128 * LDR)             // 9216 words: one resident 128x128-half tile
#define STG_W  (128 * 8)               // 1024 words: one streamed stage
// k_proj_gcn:  ef | 3 A stages | 3 B stages | bias
#define PG_SMEM_W (EF_W + 3 * STG_W + 3 * STG_W + 128)
// k_gate_fuse: corr | baseR | 3 A stages | 3 B stages | 2 biases
#define GF_SMEM_W (2 * EF_W + 3 * STG_W + 3 * STG_W + 256)

// ---------------- weight prep: half Wt[n][permk(k)] = W[k][n] -------------------
__global__ void wprep(const float* __restrict__ W0, const float* __restrict__ W1,
                      const float* __restrict__ W2, const float* __restrict__ W3,
                      __half* __restrict__ T0, __half* __restrict__ T1,
                      __half* __restrict__ T2, __half* __restrict__ T3)
{
    __shared__ float s[32][33];
    int b = blockIdx.x;
    const float* W; __half* T; int K;
    if (b < 8)       { W = W0; T = T0; K = 64;  }
    else if (b < 24) { W = W1; T = T1; K = 128; b -= 8;  }
    else if (b < 56) { W = W2; T = T2; K = 256; b -= 24; }
    else             { W = W3; T = T3; K = 256; b -= 56; }
    const int k0 = (b >> 2) * 32, n0 = (b & 3) * 32;
    const int tx = threadIdx.x & 31, ty = threadIdx.x >> 5;
#pragma unroll
    for (int i = 0; i < 4; i++)
        s[ty + i * 8][tx] = W[(size_t)(k0 + ty + i * 8) * HID + n0 + tx];
    __syncthreads();
    const int k = k0 + tx;
    const int col = ((k >> 4) << 4) + (perm8((k & 15) >> 1) << 1) + (k & 1);
#pragma unroll
    for (int i = 0; i < 4; i++) {
        const int n = n0 + ty + i * 8;
        T[(size_t)n * K + col] = __float2half(s[tx][ty + i * 8]);
    }
}

// ---------------- activation convert: fp32 -> k-permuted fp16 -------------------
template<int WPR>
__global__ void cvt_half(const float2* __restrict__ in, uint32_t* __restrict__ out,
                         int total_words)
{
    int idx = blockIdx.x * blockDim.x + threadIdx.x;
    if (idx >= total_words) return;
    const int row = idx / WPR, w = idx % WPR;
    const float2 v = in[idx];
    const __half2 h = __floats2half2_rn(v.x, v.y);
    out[(size_t)row * WPR + permw(w)] = *(const uint32_t*)&h;
}

// ================================================================================
// Fused kernel 1: ef = relu(evh @ Wp + bp) [fp16 smem-resident]; xg = ef @ Wgcn
// (R10 proven configuration: BK=16, 3-stage cp.async pipeline)
// ================================================================================
__global__ void __launch_bounds__(256, 2)
k_proj_gcn(const uint32_t* __restrict__ evh, const __half* __restrict__ Wtp,
           const float* __restrict__ bp, const __half* __restrict__ Wtg,
           uint32_t* __restrict__ xgh, int M)
{
    extern __shared__ uint32_t dsm[];
    uint32_t* ef = dsm;
    uint32_t* As = dsm + EF_W;
    uint32_t* Bs = As + 3 * STG_W;
    float*    sb = (float*)(Bs + 3 * STG_W);

    const int tid   = threadIdx.x;
    const int wid   = tid >> 5, lane = tid & 31;
    const int warpM = wid & 3,  warpN = wid >> 2;
    const int lr    = lane >> 2, lc = lane & 3;
    const int m0    = blockIdx.x * 128;

    if (tid < 128) sb[tid] = bp[tid];

    const uint32_t as_b = smem_u32(As);
    const uint32_t bs_b = smem_u32(Bs);

    float c[2][8][4];
#pragma unroll
    for (int mi = 0; mi < 2; mi++)
#pragma unroll
        for (int ni = 0; ni < 8; ni++)
#pragma unroll
            for (int j = 0; j < 4; j++) c[mi][ni][j] = 0.f;

    auto issueA = [&](int st, int ch) {
        const int r = tid >> 1, q = tid & 1;
        int gr = m0 + r; if (gr > M - 1) gr = M - 1;
        cp16(as_b + (uint32_t)(st * STG_W + r * 8 + q * 4) * 4,
             evh + (size_t)gr * 32 + ch * 8 + q * 4);
    };
    auto issueB = [&](int st, int ch, const __half* Wt, int WPRW) {
        const int n = tid >> 1, q = tid & 1;
        cp16(bs_b + (uint32_t)(st * STG_W + n * 8 + q * 4) * 4,
             Wt + (size_t)n * (WPRW * 2) + (ch * 8 + q * 4) * 2);
    };
    auto compute = [&](const uint32_t* Ab, int lda, int wb, const uint32_t* Bb) {
        uint32_t a0[2], a1[2], a2[2], a3[2];
#pragma unroll
        for (int mi = 0; mi < 2; mi++) {
            const int row = warpM * 32 + mi * 16 + lr;
            const uint2 lo = *(const uint2*)(Ab + row * lda + wb + 2 * lc);
            const uint2 hi = *(const uint2*)(Ab + (row + 8) * lda + wb + 2 * lc);
            a0[mi] = lo.x; a1[mi] = hi.x; a2[mi] = lo.y; a3[mi] = hi.y;
        }
#pragma unroll
        for (int ni = 0; ni < 8; ni++) {
            const uint2 bb = *(const uint2*)(Bb + (warpN * 64 + ni * 8 + lr) * 8 + 2 * lc);
#pragma unroll
            for (int mi = 0; mi < 2; mi++)
                mma_f16(c[mi][ni], a0[mi], a1[mi], a2[mi], a3[mi], bb.x, bb.y);
        }
    };

    // ---- phase 1: K=64, 4 chunks, 3-stage pipeline
    issueA(0, 0); issueB(0, 0, Wtp, 32); cp_commit();
    issueA(1, 1); issueB(1, 1, Wtp, 32); cp_commit();
    for (int i = 0; i < 4; i++) {
        if (i < 3) cp_wait<1>(); else cp_wait<0>();
        __syncthreads();
        if (i + 2 < 4) { issueA((i + 2) % 3, i + 2); issueB((i + 2) % 3, i + 2, Wtp, 32); cp_commit(); }
        compute(As + (i % 3) * STG_W, 8, 0, Bs + (i % 3) * STG_W);
    }
    __syncthreads();

    // prefetch phase-2 B chunks 0,1
    issueB(0, 0, Wtg, 64); cp_commit();
    issueB(1, 1, Wtg, 64); cp_commit();

    // ---- epilogue 1: relu(v+b) -> permuted fp16 into ef
#pragma unroll
    for (int mi = 0; mi < 2; mi++)
#pragma unroll
        for (int half = 0; half < 2; half++) {
            const int row = warpM * 32 + mi * 16 + lr + half * 8;
#pragma unroll
            for (int ni = 0; ni < 8; ni++) {
                const int col = warpN * 64 + ni * 8 + lc * 2;
                const float v0 = fmaxf(c[mi][ni][half * 2 + 0] + sb[col + 0], 0.f);
                const float v1 = fmaxf(c[mi][ni][half * 2 + 1] + sb[col + 1], 0.f);
                const __half2 h = __floats2half2_rn(v0, v1);
                ef[row * LDR + permw(col >> 1)] = *(const uint32_t*)&h;
            }
        }

#pragma unroll
    for (int mi = 0; mi < 2; mi++)
#pragma unroll
        for (int ni = 0; ni < 8; ni++)
#pragma unroll
            for (int j = 0; j < 4; j++) c[mi][ni][j] = 0.f;

    // ---- phase 2: xg = ef @ Wgcn, K=128, A resident
    for (int i = 0; i < 8; i++) {
        if (i < 7) cp_wait<1>(); else cp_wait<0>();
        __syncthreads();
        if (i + 2 < 8) { issueB((i + 2) % 3, i + 2, Wtg, 64); cp_commit(); }
        compute(ef, LDR, i * 8, Bs + (i % 3) * STG_W);
    }

    // ---- epilogue 2: xg fp16 plain layout
#pragma unroll
    for (int mi = 0; mi < 2; mi++)
#pragma unroll
        for (int half = 0; half < 2; half++) {
            const int row = m0 + warpM * 32 + mi * 16 + lr + half * 8;
            if (row >= M) continue;
#pragma unroll
            for (int ni = 0; ni < 8; ni++) {
                const int col = warpN * 64 + ni * 8 + lc * 2;
                const __half2 h = __floats2half2_rn(c[mi][ni][half * 2 + 0],
                                                    c[mi][ni][half * 2 + 1]);
                xgh[(size_t)row * 64 + (col >> 1)] = *(const uint32_t*)&h;
            }
        }
}

// ================================================================================
// Fused kernel 2: gate GEMM -> corrected (smem) -> fuse GEMM (R10 proven design)
// ================================================================================
__global__ void __launch_bounds__(256, 2)
k_gate_fuse(const uint32_t* __restrict__ baseh, const uint32_t* __restrict__ diffh,
            const __half* __restrict__ Wtg, const float* __restrict__ bg,
            const __half* __restrict__ Wtf, const float* __restrict__ bf,
            float* __restrict__ out, int M)
{
    extern __shared__ uint32_t dsm[];
    uint32_t* corr  = dsm;
    uint32_t* baseR = dsm + EF_W;
    uint32_t* As    = baseR + EF_W;
    uint32_t* Bs    = As + 3 * STG_W;
    float*    sbg   = (float*)(Bs + 3 * STG_W);
    float*    sbf   = sbg + 128;

    const int tid   = threadIdx.x;
    const int wid   = tid >> 5, lane = tid & 31;
    const int warpM = wid & 3,  warpN = wid >> 2;
    const int lr    = lane >> 2, lc = lane & 3;
    const int m0    = blockIdx.x * 128;

    if (tid < 128) { sbg[tid] = bg[tid]; sbf[tid] = bf[tid]; }

    const uint32_t br_b = smem_u32(baseR);
    const uint32_t as_b = smem_u32(As);
    const uint32_t bs_b = smem_u32(Bs);

    float c[2][8][4];
#pragma unroll
    for (int mi = 0; mi < 2; mi++)
#pragma unroll
        for (int ni = 0; ni < 8; ni++)
#pragma unroll
            for (int j = 0; j < 4; j++) c[mi][ni][j] = 0.f;

    auto issueA = [&](int ch) {
        const int r = tid >> 1, q = tid & 1;
        int gr = m0 + r; if (gr > M - 1) gr = M - 1;
        if (ch < 8) {
            cp16(br_b + (uint32_t)(r * LDR + ch * 8 + q * 4) * 4,
                 baseh + (size_t)gr * 64 + ch * 8 + q * 4);
        } else {
            cp16(as_b + (uint32_t)(((ch - 8) % 3) * STG_W + r * 8 + q * 4) * 4,
                 diffh + (size_t)gr * 64 + (ch - 8) * 8 + q * 4);
        }
    };
    auto issueB = [&](int ch, const __half* Wt) {
        const int n = tid >> 1, q = tid & 1;
        cp16(bs_b + (uint32_t)((ch % 3) * STG_W + n * 8 + q * 4) * 4,
             Wt + (size_t)n * 256 + (ch * 8 + q * 4) * 2);
    };
    auto compute = [&](const uint32_t* Ab, int lda, int wb, const uint32_t* Bb) {
        uint32_t a0[2], a1[2], a2[2], a3[2];
#pragma unroll
        for (int mi = 0; mi < 2; mi++) {
            const int row = warpM * 32 + mi * 16 + lr;
            const uint2 lo = *(const uint2*)(Ab + row * lda + wb + 2 * lc);
            const uint2 hi = *(const uint2*)(Ab + (row + 8) * lda + wb + 2 * lc);
            a0[mi] = lo.x; a1[mi] = hi.x; a2[mi] = lo.y; a3[mi] = hi.y;
        }
#pragma unroll
        for (int ni = 0; ni < 8; ni++) {
            const uint2 bb = *(const uint2*)(Bb + (warpN * 64 + ni * 8 + lr) * 8 + 2 * lc);
#pragma unroll
            for (int mi = 0; mi < 2; mi++)
                mma_f16(c[mi][ni], a0[mi], a1[mi], a2[mi], a3[mi], bb.x, bb.y);
        }
    };

    // ---- phase A: gate GEMM, K=256 (16 chunks)
    issueA(0); issueB(0, Wtg); cp_commit();
    issueA(1); issueB(1, Wtg); cp_commit();
    for (int i = 0; i < 16; i++) {
        if (i < 15) cp_wait<1>(); else cp_wait<0>();
        __syncthreads();
        if (i + 2 < 16) { issueA(i + 2); issueB(i + 2, Wtg); cp_commit(); }
        if (i < 8) compute(baseR, LDR, i * 8, Bs + (i % 3) * STG_W);
        else       compute(As + ((i - 8) % 3) * STG_W, 8, 0, Bs + (i % 3) * STG_W);
    }
    __syncthreads();

    // prefetch fuse B chunks 0,1
    issueB(0, Wtf); cp_commit();
    issueB(1, Wtf); cp_commit();

    // ---- gate epilogue: corrected -> permuted fp16 in smem
#pragma unroll
    for (int mi = 0; mi < 2; mi++)
#pragma unroll
        for (int half = 0; half < 2; half++) {
            const int lrow = warpM * 32 + mi * 16 + lr + half * 8;
            const int row  = m0 + lrow;
            const size_t rbase = (size_t)(row < M ? row : M - 1) * 64;
#pragma unroll
            for (int ni = 0; ni < 8; ni++) {
                const int col = warpN * 64 + ni * 8 + lc * 2;
                const int pw  = permw(col >> 1);
                const uint32_t ub = baseR[lrow * LDR + pw];
                const uint32_t ud = diffh[rbase + pw];
                const float2 b2 = __half22float2(*(const __half2*)&ub);
                const float2 d2 = __half22float2(*(const __half2*)&ud);
                const float g0 = 1.f / (1.f + __expf(-(c[mi][ni][half * 2 + 0] + sbg[col + 0])));
                const float g1 = 1.f / (1.f + __expf(-(c[mi][ni][half * 2 + 1] + sbg[col + 1])));
                const float v0 = fmaf(d2.x - b2.x, g0, b2.x);
                const float v1 = fmaf(d2.y - b2.y, g1, b2.y);
                const __half2 h = __floats2half2_rn(v0, v1);
                corr[lrow * LDR + pw] = *(const uint32_t*)&h;
            }
        }

#pragma unroll
    for (int mi = 0; mi < 2; mi++)
#pragma unroll
        for (int ni = 0; ni < 8; ni++)
#pragma unroll
            for (int j = 0; j < 4; j++) c[mi][ni][j] = 0.f;

    // ---- phase B: fuse GEMM, K=256; A entirely smem-resident (baseR then corr)
    for (int i = 0; i < 16; i++) {
        if (i < 15) cp_wait<1>(); else cp_wait<0>();
        __syncthreads();
        if (i + 2 < 16) { issueB(i + 2, Wtf); cp_commit(); }
        if (i < 8) compute(baseR, LDR, i * 8, Bs + (i % 3) * STG_W);
        else       compute(corr, LDR, (i - 8) * 8, Bs + (i % 3) * STG_W);
    }

    // ---- fuse epilogue: relu(v + bf) -> out (fp32)
#pragma unroll
    for (int mi = 0; mi < 2; mi++)
#pragma unroll
        for (int half = 0; half < 2; half++) {
            const int row = m0 + warpM * 32 + mi * 16 + lr + half * 8;
            if (row >= M) continue;
#pragma unroll
            for (int ni = 0; ni < 8; ni++) {
                const int col = warpN * 64 + ni * 8 + lc * 2;
                *(float2*)(out + (size_t)row * HID + col) =
                    make_float2(fmaxf(c[mi][ni][half * 2 + 0] + sbf[col + 0], 0.f),
                                fmaxf(c[mi][ni][half * 2 + 1] + sbf[col + 1], 0.f));
            }
        }
}

// ---------------- per-block edge-dtype detection --------------------------------
// int64 ids < 2^31 => all odd 32-bit words zero; int32 => some sampled word nonzero.
__device__ __forceinline__ int detect_is32(const void* ei) {
    const unsigned* p = (const unsigned*)ei;
    int any = 0;
    for (int i = threadIdx.x; i < 256; i += blockDim.x)
        any |= (p[2 * i + 1] != 0u);
    return __syncthreads_or(any);
}

// ---------------- degree / CSR ---------------------------------------------------
__global__ void count_deg(const void* __restrict__ ei, int E) {
    const int is32 = detect_is32(ei);
    int e = blockIdx.x * blockDim.x + threadIdx.x;
    if (e >= E) return;
    int d = is32 ? ((const int*)ei)[(size_t)E + e]
                 : (int)((const long long*)ei)[(size_t)E + e];
    atomicAdd(&g_deg[d], 1);
}
__global__ void scan1(int n) {
    __shared__ int sh[512];
    int i = blockIdx.x * 512 + threadIdx.x;
    int v = (i < n) ? g_deg[i] : 0;
    if (i < n) g_dis[i] = rsqrtf((float)(v + 1));
    sh[threadIdx.x] = v;
    __syncthreads();
    for (int off = 256; off > 0; off >>= 1) {
        if (threadIdx.x < off) sh[threadIdx.x] += sh[threadIdx.x + off];
        __syncthreads();
    }
    if (threadIdx.x == 0) g_bsum[blockIdx.x] = sh[0];
}
__global__ void scan2(int nb) {
    __shared__ int sh[1024];
    int tid = threadIdx.x;
    int v = (tid < nb) ? g_bsum[tid] : 0;
    sh[tid] = v;
    __syncthreads();
    for (int off = 1; off < 1024; off <<= 1) {
        int t = (tid >= off) ? sh[tid - off] : 0;
        __syncthreads();
        sh[tid] += t;
        __syncthreads();
    }
    if (tid < nb) g_bsum[tid] = sh[tid] - v;
}
__global__ void scan3(int n) {
    __shared__ int sh[512];
    int tid = threadIdx.x;
    int i = blockIdx.x * 512 + tid;
    int v = (i < n) ? g_deg[i] : 0;
    sh[tid] = v;
    __syncthreads();
    for (int off = 1; off < 512; off <<= 1) {
        int t = (tid >= off) ? sh[tid - off] : 0;
        __syncthreads();
        sh[tid] += t;
        __syncthreads();
    }
    if (i < n) {
        int rs = g_bsum[blockIdx.x] + sh[tid] - v;
        g_rowstart[i] = rs;
        g_cursor[i]   = rs;
    }
}
__global__ void fill_csr(const void* __restrict__ ei, int E) {
    const int is32 = detect_is32(ei);
    int e = blockIdx.x * blockDim.x + threadIdx.x;
    if (e >= E) return;
    int s, d;
    if (is32) {
        s = ((const int*)ei)[e];
        d = ((const int*)ei)[(size_t)E + e];
    } else {
        s = (int)((const long long*)ei)[e];
        d = (int)((const long long*)ei)[(size_t)E + e];
    }
    int pos = atomicAdd(&g_cursor[d], 1);
    g_csr[pos] = s;
}

// ---------------- aggregation: warp per node, fp16 gather-sum --------------------
__device__ __forceinline__ float4 h4f(uint2 v) {
    const float2 f0 = __half22float2(*(const __half2*)&v.x);
    const float2 f1 = __half22float2(*(const __half2*)&v.y);
    return make_float4(f0.x, f0.y, f1.x, f1.y);
}
__global__ void aggregate(const float* __restrict__ b_gcn, int n) {
    int gw   = (blockIdx.x * blockDim.x + threadIdx.x) >> 5;
    int lane = threadIdx.x & 31;
    if (gw >= n) return;
    const int node = gw;
    const uint2* __restrict__ xg2 = (const uint2*)g_xgh;

    const float4 selfv = h4f(xg2[(size_t)node * 32 + lane]);
    const float  dn    = g_dis[node];
    const int    s0    = g_rowstart[node];
    const int    cnt   = g_deg[node];

    float4 acc = make_float4(0.f, 0.f, 0.f, 0.f);
    int e = s0, eend = s0 + cnt;
    for (; e + 1 < eend; e += 2) {
        const int s1 = g_csr[e], s2 = g_csr[e + 1];
        const float w1 = g_dis[s1], w2 = g_dis[s2];
        const float4 v1 = h4f(xg2[(size_t)s1 * 32 + lane]);
        const float4 v2 = h4f(xg2[(size_t)s2 * 32 + lane]);
        acc.x += v1.x * w1 + v2.x * w2;
        acc.y += v1.y * w1 + v2.y * w2;
        acc.z += v1.z * w1 + v2.z * w2;
        acc.w += v1.w * w1 + v2.w * w2;
    }
    if (e < eend) {
        const int s1 = g_csr[e];
        const float w1 = g_dis[s1];
        const float4 v1 = h4f(xg2[(size_t)s1 * 32 + lane]);
        acc.x += v1.x * w1; acc.y += v1.y * w1;
        acc.z += v1.z * w1; acc.w += v1.w * w1;
    }
    const float sw = dn * dn;
    const float4 b = ((const float4*)b_gcn)[lane];
    float4 o;
    o.x = fmaxf(acc.x * dn + selfv.x * sw + b.x, 0.f);
    o.y = fmaxf(acc.y * dn + selfv.y * sw + b.y, 0.f);
    o.z = fmaxf(acc.z * dn + selfv.z * sw + b.z, 0.f);
    o.w = fmaxf(acc.w * dn + selfv.w * sw + b.w, 0.f);
    const __half2 h0 = __floats2half2_rn(o.x, o.y);
    const __half2 h1 = __floats2half2_rn(o.z, o.w);
    uint32_t* drow = g_diffh + (size_t)node * 64;
    drow[permw(2 * lane)]     = *(const uint32_t*)&h0;
    drow[permw(2 * lane + 1)] = *(const uint32_t*)&h1;
}

// ---------------- launcher --------------------------------------------------------
extern "C" void kernel_launch(void* const* d_in, const int* in_sizes, int n_in,
                              void* d_out, int out_size)
{
    const float* base   = (const float*)d_in[0];
    const float* ev     = (const float*)d_in[1];
    const void*  ei     = d_in[2];
    const float* W_proj = (const float*)d_in[3];
    const float* b_proj = (const float*)d_in[4];
    const float* W_gcn  = (const float*)d_in[5];
    const float* b_gcn  = (const float*)d_in[6];
    const float* W_gate = (const float*)d_in[7];
    const float* b_gate = (const float*)d_in[8];
    const float* W_fuse = (const float*)d_in[9];
    const float* b_fuse = (const float*)d_in[10];

    const int N = in_sizes[0] / HID;
    const int E = in_sizes[2] / 2;

    uint32_t *p_xgh, *p_diffh, *p_evh, *p_baseh;
    __half *p_wtp, *p_wtg, *p_wtga, *p_wtf;
    int *p_deg;
    cudaGetSymbolAddress((void**)&p_xgh,   g_xgh);
    cudaGetSymbolAddress((void**)&p_diffh, g_diffh);
    cudaGetSymbolAddress((void**)&p_evh,   g_evh);
    cudaGetSymbolAddress((void**)&p_baseh, g_baseh);
    cudaGetSymbolAddress((void**)&p_wtp,   g_wt_proj);
    cudaGetSymbolAddress((void**)&p_wtg,   g_wt_gcn);
    cudaGetSymbolAddress((void**)&p_wtga,  g_wt_gate);
    cudaGetSymbolAddress((void**)&p_wtf,   g_wt_fuse);
    cudaGetSymbolAddress((void**)&p_deg,   g_deg);

    cudaFuncSetAttribute(k_proj_gcn,  cudaFuncAttributeMaxDynamicSharedMemorySize, PG_SMEM_W * 4);
    cudaFuncSetAttribute(k_gate_fuse, cudaFuncAttributeMaxDynamicSharedMemorySize, GF_SMEM_W * 4);

    const int gT = (N + 127) / 128;
    const int gE = (E + 255) / 256;
    const int nb = (N + 511) / 512;

    // single side stream for CSR chain + base convert (destroyed before return)
    cudaStream_t side;
    cudaEvent_t evFork, evJoin, evJoin2;
    cudaStreamCreateWithFlags(&side, cudaStreamNonBlocking);
    cudaEventCreateWithFlags(&evFork,  cudaEventDisableTiming);
    cudaEventCreateWithFlags(&evJoin,  cudaEventDisableTiming);
    cudaEventCreateWithFlags(&evJoin2, cudaEventDisableTiming);

    cudaEventRecord(evFork, 0);
    cudaStreamWaitEvent(side, evFork, 0);

    // --- side: CSR build, then base convert (joined separately)
    cudaMemsetAsync(p_deg, 0, (size_t)N * sizeof(int), side);
    count_deg<<<gE, 256, 0, side>>>(ei, E);
    scan1<<<nb, 512, 0, side>>>(N);
    scan2<<<1, 1024, 0, side>>>(nb);
    scan3<<<nb, 512, 0, side>>>(N);
    fill_csr<<<gE, 256, 0, side>>>(ei, E);
    cudaEventRecord(evJoin, side);                      // CSR ready
    cvt_half<64><<<(N * 64 + 255) / 256, 256, 0, side>>>((const float2*)base, p_baseh, N * 64);
    cudaEventRecord(evJoin2, side);                     // baseh ready

    // --- main: weight prep + ev convert + fused proj/gcn GEMM (overlaps side)
    wprep<<<88, 256>>>(W_proj, W_gcn, W_gate, W_fuse, p_wtp, p_wtg, p_wtga, p_wtf);
    cvt_half<32><<<(N * 32 + 255) / 256, 256>>>((const float2*)ev, p_evh, N * 32);
    k_proj_gcn<<<gT, 256, PG_SMEM_W * 4>>>(p_evh, p_wtp, b_proj, p_wtg, p_xgh, N);

    // aggregate needs xgh (main) + CSR (side); overlaps cvt_base on the side stream
    cudaStreamWaitEvent(0, evJoin, 0);
    aggregate<<<(N * 32 + 255) / 256, 256>>>(b_gcn, N);

    // gate_fuse additionally needs baseh
    cudaStreamWaitEvent(0, evJoin2, 0);
    k_gate_fuse<<<gT, 256, GF_SMEM_W * 4>>>(p_baseh, p_diffh, p_wtga, b_gate,
                                            p_wtf, b_fuse, (float*)d_out, N);

    // release resources created this call (graph retains captured dependencies)
    cudaEventDestroy(evFork);
    cudaEventDestroy(evJoin);
    cudaEventDestroy(evJoin2);
    cudaStreamDestroy(side);
}

// round 13
// speedup vs baseline: 1.7725x; 1.0154x over previous
#include <cuda_runtime.h>
#include <cuda_fp16.h>
#include <cstdint>

#define NMAX 100000
#define EMAX 1600000
#define HID 128

// ---------------- scratch (device globals; no allocations allowed) ----------
__device__ uint32_t g_xgh  [(size_t)NMAX * 64];   // xg fp16, plain layout
__device__ uint32_t g_diffh[(size_t)NMAX * 64];   // diffused fp16, k-permuted
__device__ uint32_t g_evh  [(size_t)NMAX * 32];   // ev fp16, k-permuted
__device__ uint32_t g_baseh[(size_t)NMAX * 64];   // base fp16, k-permuted
__device__ int   g_deg[NMAX];
__device__ float g_dis[NMAX];
__device__ int   g_rowstart[NMAX];
__device__ int   g_cursor[NMAX];
__device__ int   g_csr[EMAX];
__device__ int   g_bsum[1024];
// fp16 transposed + k-permuted weights [128 n][K k]
__device__ __half g_wt_proj[128 * 64];
__device__ __half g_wt_gcn [128 * 128];
__device__ __half g_wt_gate[128 * 256];
__device__ __half g_wt_fuse[128 * 256];

// ---------------- PTX helpers --------------------------------------------------
__device__ __forceinline__ uint32_t smem_u32(const void* p) {
    uint32_t a;
    asm("{ .reg .u64 t; cvta.to.shared.u64 t, %1; cvt.u32.u64 %0, t; }" : "=r"(a) : "l"(p));
    return a;
}
__device__ __forceinline__ void cp16(uint32_t dst, const void* src) {
    asm volatile("cp.async.cg.shared.global [%0], [%1], 16;" :: "r"(dst), "l"(src));
}
__device__ __forceinline__ void cp_commit() {
    asm volatile("cp.async.commit_group;" ::: "memory");
}
template<int N>
__device__ __forceinline__ void cp_wait() {
    asm volatile("cp.async.wait_group %0;" :: "n"(N) : "memory");
}
__device__ __forceinline__ void mma_f16(float* c, uint32_t a0, uint32_t a1,
                                        uint32_t a2, uint32_t a3,
                                        uint32_t b0, uint32_t b1) {
    asm volatile(
        "mma.sync.aligned.m16n8k16.row.col.f32.f16.f16.f32 "
        "{%0,%1,%2,%3}, {%4,%5,%6,%7}, {%8,%9}, {%0,%1,%2,%3};"
        : "+f"(c[0]), "+f"(c[1]), "+f"(c[2]), "+f"(c[3])
        : "r"(a0), "r"(a1), "r"(a2), "r"(a3), "r"(b0), "r"(b1));
}

// k-word permutation within each 8-word group: pairs (w, w+4) become adjacent
__device__ __forceinline__ int perm8(int w) { return (w < 4) ? 2 * w : 2 * (w - 4) + 1; }
__device__ __forceinline__ int permw(int w) { return ((w >> 3) << 3) + perm8(w & 7); }

// smem geometry (uint32 words)
#define LDR 72                  // 128-half resident rows (+8 pad): conflict-free
#define LDE 40                  // 64-half resident rows (+8 pad): conflict-free
#define EF_W   (128 * LDR)      // 9216 words
#define EV_W   (128 * LDE)      // 5120 words
#define STG_W  (128 * 8)        // 1024 words: one streamed B stage
// k_proj_gcn:  ef | evR | 3 B stages | bias
#define PG_SMEM_W (EF_W + EV_W + 3 * STG_W + 128)
// k_gate_fuse: diffR(->corr) | baseR | 3 B stages | 2 biases
#define GF_SMEM_W (2 * EF_W + 3 * STG_W + 256)

// ---------------- weight prep: half Wt[n][permk(k)] = W[k][n] -------------------
__global__ void wprep(const float* __restrict__ W0, const float* __restrict__ W1,
                      const float* __restrict__ W2, const float* __restrict__ W3,
                      __half* __restrict__ T0, __half* __restrict__ T1,
                      __half* __restrict__ T2, __half* __restrict__ T3)
{
    __shared__ float s[32][33];
    int b = blockIdx.x;
    const float* W; __half* T; int K;
    if (b < 8)       { W = W0; T = T0; K = 64;  }
    else if (b < 24) { W = W1; T = T1; K = 128; b -= 8;  }
    else if (b < 56) { W = W2; T = T2; K = 256; b -= 24; }
    else             { W = W3; T = T3; K = 256; b -= 56; }
    const int k0 = (b >> 2) * 32, n0 = (b & 3) * 32;
    const int tx = threadIdx.x & 31, ty = threadIdx.x >> 5;
#pragma unroll
    for (int i = 0; i < 4; i++)
        s[ty + i * 8][tx] = W[(size_t)(k0 + ty + i * 8) * HID + n0 + tx];
    __syncthreads();
    const int k = k0 + tx;
    const int col = ((k >> 4) << 4) + (perm8((k & 15) >> 1) << 1) + (k & 1);
#pragma unroll
    for (int i = 0; i < 4; i++) {
        const int n = n0 + ty + i * 8;
        T[(size_t)n * K + col] = __float2half(s[tx][ty + i * 8]);
    }
}

// ---------------- activation convert: fp32 -> k-permuted fp16 -------------------
template<int WPR>
__global__ void cvt_half(const float2* __restrict__ in, uint32_t* __restrict__ out,
                         int total_words)
{
    int idx = blockIdx.x * blockDim.x + threadIdx.x;
    if (idx >= total_words) return;
    const int row = idx / WPR, w = idx % WPR;
    const float2 v = in[idx];
    const __half2 h = __floats2half2_rn(v.x, v.y);
    out[(size_t)row * WPR + permw(w)] = *(const uint32_t*)&h;
}

// ================================================================================
// Fused kernel 1: ef = relu(evR @ Wp + bp) [fp16 smem-resident]; xg = ef @ Wgcn
// A operands fully smem-resident; only B streams (BK=16, 3-stage).
// ================================================================================
__global__ void __launch_bounds__(256, 2)
k_proj_gcn(const uint32_t* __restrict__ evh, const __half* __restrict__ Wtp,
           const float* __restrict__ bp, const __half* __restrict__ Wtg,
           uint32_t* __restrict__ xgh, int M)
{
    extern __shared__ uint32_t dsm[];
    uint32_t* ef  = dsm;
    uint32_t* evR = dsm + EF_W;
    uint32_t* Bs  = evR + EV_W;
    float*    sb  = (float*)(Bs + 3 * STG_W);

    const int tid   = threadIdx.x;
    const int wid   = tid >> 5, lane = tid & 31;
    const int warpM = wid & 3,  warpN = wid >> 2;
    const int lr    = lane >> 2, lc = lane & 3;
    const int m0    = blockIdx.x * 128;

    if (tid < 128) sb[tid] = bp[tid];

    const uint32_t ev_b = smem_u32(evR);
    const uint32_t bs_b = smem_u32(Bs);

    float c[2][8][4];
#pragma unroll
    for (int mi = 0; mi < 2; mi++)
#pragma unroll
        for (int ni = 0; ni < 8; ni++)
#pragma unroll
            for (int j = 0; j < 4; j++) c[mi][ni][j] = 0.f;

    // ---- group 0: whole evR tile (128 rows x 32 words), 4 cp16/thread
#pragma unroll
    for (int i = 0; i < 4; i++) {
        const int slot = tid + i * 256;
        const int r = slot >> 3, q = slot & 7;
        int gr = m0 + r; if (gr > M - 1) gr = M - 1;
        cp16(ev_b + (uint32_t)(r * LDE + q * 4) * 4, evh + (size_t)gr * 32 + q * 4);
    }
    cp_commit();

    auto issueB = [&](int st, int ch, const __half* Wt, int WPRW) {
        const int n = tid >> 1, q = tid & 1;
        cp16(bs_b + (uint32_t)(st * STG_W + n * 8 + q * 4) * 4,
             Wt + (size_t)n * (WPRW * 2) + (ch * 8 + q * 4) * 2);
    };
    auto compute = [&](const uint32_t* Ab, int lda, int wb, const uint32_t* Bb) {
        uint32_t a0[2], a1[2], a2[2], a3[2];
#pragma unroll
        for (int mi = 0; mi < 2; mi++) {
            const int row = warpM * 32 + mi * 16 + lr;
            const uint2 lo = *(const uint2*)(Ab + row * lda + wb + 2 * lc);
            const uint2 hi = *(const uint2*)(Ab + (row + 8) * lda + wb + 2 * lc);
            a0[mi] = lo.x; a1[mi] = hi.x; a2[mi] = lo.y; a3[mi] = hi.y;
        }
#pragma unroll
        for (int ni = 0; ni < 8; ni++) {
            const uint2 bb = *(const uint2*)(Bb + (warpN * 64 + ni * 8 + lr) * 8 + 2 * lc);
#pragma unroll
            for (int mi = 0; mi < 2; mi++)
                mma_f16(c[mi][ni], a0[mi], a1[mi], a2[mi], a3[mi], bb.x, bb.y);
        }
    };

    // ---- phase 1: K=64, 4 B chunks, 3-stage pipeline; A = evR resident
    issueB(0, 0, Wtp, 32); cp_commit();
    issueB(1, 1, Wtp, 32); cp_commit();
    for (int i = 0; i < 4; i++) {
        if (i < 3) cp_wait<1>(); else cp_wait<0>();
        __syncthreads();
        if (i + 2 < 4) { issueB((i + 2) % 3, i + 2, Wtp, 32); cp_commit(); }
        compute(evR, LDE, i * 8, Bs + (i % 3) * STG_W);
    }
    __syncthreads();

    // prefetch phase-2 B chunks 0,1
    issueB(0, 0, Wtg, 64); cp_commit();
    issueB(1, 1, Wtg, 64); cp_commit();

    // ---- epilogue 1: relu(v+b) -> permuted fp16 into ef
#pragma unroll
    for (int mi = 0; mi < 2; mi++)
#pragma unroll
        for (int half = 0; half < 2; half++) {
            const int row = warpM * 32 + mi * 16 + lr + half * 8;
#pragma unroll
            for (int ni = 0; ni < 8; ni++) {
                const int col = warpN * 64 + ni * 8 + lc * 2;
                const float v0 = fmaxf(c[mi][ni][half * 2 + 0] + sb[col + 0], 0.f);
                const float v1 = fmaxf(c[mi][ni][half * 2 + 1] + sb[col + 1], 0.f);
                const __half2 h = __floats2half2_rn(v0, v1);
                ef[row * LDR + permw(col >> 1)] = *(const uint32_t*)&h;
            }
        }

#pragma unroll
    for (int mi = 0; mi < 2; mi++)
#pragma unroll
        for (int ni = 0; ni < 8; ni++)
#pragma unroll
            for (int j = 0; j < 4; j++) c[mi][ni][j] = 0.f;

    // ---- phase 2: xg = ef @ Wgcn, K=128 (8 chunks), A = ef resident
    for (int i = 0; i < 8; i++) {
        if (i < 7) cp_wait<1>(); else cp_wait<0>();
        __syncthreads();
        if (i + 2 < 8) { issueB((i + 2) % 3, i + 2, Wtg, 64); cp_commit(); }
        compute(ef, LDR, i * 8, Bs + (i % 3) * STG_W);
    }

    // ---- epilogue 2: xg fp16 plain layout
#pragma unroll
    for (int mi = 0; mi < 2; mi++)
#pragma unroll
        for (int half = 0; half < 2; half++) {
            const int row = m0 + warpM * 32 + mi * 16 + lr + half * 8;
            if (row >= M) continue;
#pragma unroll
            for (int ni = 0; ni < 8; ni++) {
                const int col = warpN * 64 + ni * 8 + lc * 2;
                const __half2 h = __floats2half2_rn(c[mi][ni][half * 2 + 0],
                                                    c[mi][ni][half * 2 + 1]);
                xgh[(size_t)row * 64 + (col >> 1)] = *(const uint32_t*)&h;
            }
        }
}

// ================================================================================
// Fused kernel 2: gate GEMM -> corrected (in place over diffR) -> fuse GEMM.
// baseR + diffR both smem-resident from the start; only B streams.
// ================================================================================
__global__ void __launch_bounds__(256, 2)
k_gate_fuse(const uint32_t* __restrict__ baseh, const uint32_t* __restrict__ diffh,
            const __half* __restrict__ Wtg, const float* __restrict__ bg,
            const __half* __restrict__ Wtf, const float* __restrict__ bf,
            float* __restrict__ out, int M)
{
    extern __shared__ uint32_t dsm[];
    uint32_t* diffR = dsm;              // overwritten in place by corrected
    uint32_t* baseR = dsm + EF_W;
    uint32_t* Bs    = baseR + EF_W;
    float*    sbg   = (float*)(Bs + 3 * STG_W);
    float*    sbf   = sbg + 128;

    const int tid   = threadIdx.x;
    const int wid   = tid >> 5, lane = tid & 31;
    const int warpM = wid & 3,  warpN = wid >> 2;
    const int lr    = lane >> 2, lc = lane & 3;
    const int m0    = blockIdx.x * 128;

    if (tid < 128) { sbg[tid] = bg[tid]; sbf[tid] = bf[tid]; }

    const uint32_t df_b = smem_u32(diffR);
    const uint32_t br_b = smem_u32(baseR);
    const uint32_t bs_b = smem_u32(Bs);

    float c[2][8][4];
#pragma unroll
    for (int mi = 0; mi < 2; mi++)
#pragma unroll
        for (int ni = 0; ni < 8; ni++)
#pragma unroll
            for (int j = 0; j < 4; j++) c[mi][ni][j] = 0.f;

    // ---- group 0: whole baseR + diffR tiles (8 cp16/thread each)
    {
        const int r = tid >> 1, q = tid & 1;
        int gr = m0 + r; if (gr > M - 1) gr = M - 1;
#pragma unroll
        for (int c8 = 0; c8 < 8; c8++) {
            cp16(br_b + (uint32_t)(r * LDR + c8 * 8 + q * 4) * 4,
                 baseh + (size_t)gr * 64 + c8 * 8 + q * 4);
            cp16(df_b + (uint32_t)(r * LDR + c8 * 8 + q * 4) * 4,
                 diffh + (size_t)gr * 64 + c8 * 8 + q * 4);
        }
    }
    cp_commit();

    auto issueB = [&](int ch, const __half* Wt) {
        const int n = tid >> 1, q = tid & 1;
        cp16(bs_b + (uint32_t)((ch % 3) * STG_W + n * 8 + q * 4) * 4,
             Wt + (size_t)n * 256 + (ch * 8 + q * 4) * 2);
    };
    auto compute = [&](const uint32_t* Ab, int wb, const uint32_t* Bb) {
        uint32_t a0[2], a1[2], a2[2], a3[2];
#pragma unroll
        for (int mi = 0; mi < 2; mi++) {
            const int row = warpM * 32 + mi * 16 + lr;
            const uint2 lo = *(const uint2*)(Ab + row * LDR + wb + 2 * lc);
            const uint2 hi = *(const uint2*)(Ab + (row + 8) * LDR + wb + 2 * lc);
            a0[mi] = lo.x; a1[mi] = hi.x; a2[mi] = lo.y; a3[mi] = hi.y;
        }
#pragma unroll
        for (int ni = 0; ni < 8; ni++) {
            const uint2 bb = *(const uint2*)(Bb + (warpN * 64 + ni * 8 + lr) * 8 + 2 * lc);
#pragma unroll
            for (int mi = 0; mi < 2; mi++)
                mma_f16(c[mi][ni], a0[mi], a1[mi], a2[mi], a3[mi], bb.x, bb.y);
        }
    };

    // ---- phase A: gate GEMM, K=256 (16 B chunks); A = baseR then diffR, resident
    issueB(0, Wtg); cp_commit();
    issueB(1, Wtg); cp_commit();
    for (int i = 0; i < 16; i++) {
        if (i < 15) cp_wait<1>(); else cp_wait<0>();
        __syncthreads();
        if (i + 2 < 16) { issueB(i + 2, Wtg); cp_commit(); }
        if (i < 8) compute(baseR, i * 8, Bs + (i % 3) * STG_W);
        else       compute(diffR, (i - 8) * 8, Bs + (i % 3) * STG_W);
    }
    __syncthreads();

    // prefetch fuse B chunks 0,1
    issueB(0, Wtf); cp_commit();
    issueB(1, Wtf); cp_commit();

    // ---- gate epilogue: corr = base + g*(diff-base), in place over diffR (smem)
#pragma unroll
    for (int mi = 0; mi < 2; mi++)
#pragma unroll
        for (int half = 0; half < 2; half++) {
            const int lrow = warpM * 32 + mi * 16 + lr + half * 8;
#pragma unroll
            for (int ni = 0; ni < 8; ni++) {
                const int col = warpN * 64 + ni * 8 + lc * 2;
                const int pw  = permw(col >> 1);
                const uint32_t ub = baseR[lrow * LDR + pw];
                const uint32_t ud = diffR[lrow * LDR + pw];
                const float2 b2 = __half22float2(*(const __half2*)&ub);
                const float2 d2 = __half22float2(*(const __half2*)&ud);
                const float g0 = 1.f / (1.f + __expf(-(c[mi][ni][half * 2 + 0] + sbg[col + 0])));
                const float g1 = 1.f / (1.f + __expf(-(c[mi][ni][half * 2 + 1] + sbg[col + 1])));
                const float v0 = fmaf(d2.x - b2.x, g0, b2.x);
                const float v1 = fmaf(d2.y - b2.y, g1, b2.y);
                const __half2 h = __floats2half2_rn(v0, v1);
                diffR[lrow * LDR + pw] = *(const uint32_t*)&h;
            }
        }

#pragma unroll
    for (int mi = 0; mi < 2; mi++)
#pragma unroll
        for (int ni = 0; ni < 8; ni++)
#pragma unroll
            for (int j = 0; j < 4; j++) c[mi][ni][j] = 0.f;

    // ---- phase B: fuse GEMM, K=256 (16 chunks); A = baseR then corr(diffR)
    for (int i = 0; i < 16; i++) {
        if (i < 15) cp_wait<1>(); else cp_wait<0>();
        __syncthreads();                    // orders corr writes at i=0
        if (i + 2 < 16) { issueB(i + 2, Wtf); cp_commit(); }
        if (i < 8) compute(baseR, i * 8, Bs + (i % 3) * STG_W);
        else       compute(diffR, (i - 8) * 8, Bs + (i % 3) * STG_W);
    }

    // ---- fuse epilogue: relu(v + bf) -> out (fp32)
#pragma unroll
    for (int mi = 0; mi < 2; mi++)
#pragma unroll
        for (int half = 0; half < 2; half++) {
            const int row = m0 + warpM * 32 + mi * 16 + lr + half * 8;
            if (row >= M) continue;
#pragma unroll
            for (int ni = 0; ni < 8; ni++) {
                const int col = warpN * 64 + ni * 8 + lc * 2;
                *(float2*)(out + (size_t)row * HID + col) =
                    make_float2(fmaxf(c[mi][ni][half * 2 + 0] + sbf[col + 0], 0.f),
                                fmaxf(c[mi][ni][half * 2 + 1] + sbf[col + 1], 0.f));
            }
        }
}

// ---------------- per-block edge-dtype detection --------------------------------
__device__ __forceinline__ int detect_is32(const void* ei) {
    const unsigned* p = (const unsigned*)ei;
    int any = 0;
    for (int i = threadIdx.x; i < 256; i += blockDim.x)
        any |= (p[2 * i + 1] != 0u);
    return __syncthreads_or(any);
}

// ---------------- degree / CSR ---------------------------------------------------
__global__ void count_deg(const void* __restrict__ ei, int E) {
    const int is32 = detect_is32(ei);
    int e = blockIdx.x * blockDim.x + threadIdx.x;
    if (e >= E) return;
    int d = is32 ? ((const int*)ei)[(size_t)E + e]
                 : (int)((const long long*)ei)[(size_t)E + e];
    atomicAdd(&g_deg[d], 1);
}
__global__ void scan1(int n) {
    __shared__ int sh[512];
    int i = blockIdx.x * 512 + threadIdx.x;
    int v = (i < n) ? g_deg[i] : 0;
    if (i < n) g_dis[i] = rsqrtf((float)(v + 1));
    sh[threadIdx.x] = v;
    __syncthreads();
    for (int off = 256; off > 0; off >>= 1) {
        if (threadIdx.x < off) sh[threadIdx.x] += sh[threadIdx.x + off];
        __syncthreads();
    }
    if (threadIdx.x == 0) g_bsum[blockIdx.x] = sh[0];
}
__global__ void scan2(int nb) {
    __shared__ int sh[1024];
    int tid = threadIdx.x;
    int v = (tid < nb) ? g_bsum[tid] : 0;
    sh[tid] = v;
    __syncthreads();
    for (int off = 1; off < 1024; off <<= 1) {
        int t = (tid >= off) ? sh[tid - off] : 0;
        __syncthreads();
        sh[tid] += t;
        __syncthreads();
    }
    if (tid < nb) g_bsum[tid] = sh[tid] - v;
}
__global__ void scan3(int n) {
    __shared__ int sh[512];
    int tid = threadIdx.x;
    int i = blockIdx.x * 512 + tid;
    int v = (i < n) ? g_deg[i] : 0;
    sh[tid] = v;
    __syncthreads();
    for (int off = 1; off < 512; off <<= 1) {
        int t = (tid >= off) ? sh[tid - off] : 0;
        __syncthreads();
        sh[tid] += t;
        __syncthreads();
    }
    if (i < n) {
        int rs = g_bsum[blockIdx.x] + sh[tid] - v;
        g_rowstart[i] = rs;
        g_cursor[i]   = rs;
    }
}
__global__ void fill_csr(const void* __restrict__ ei, int E) {
    const int is32 = detect_is32(ei);
    int e = blockIdx.x * blockDim.x + threadIdx.x;
    if (e >= E) return;
    int s, d;
    if (is32) {
        s = ((const int*)ei)[e];
        d = ((const int*)ei)[(size_t)E + e];
    } else {
        s = (int)((const long long*)ei)[e];
        d = (int)((const long long*)ei)[(size_t)E + e];
    }
    int pos = atomicAdd(&g_cursor[d], 1);
    g_csr[pos] = s;
}

// ---------------- aggregation: warp per node, fp16 gather-sum --------------------
__device__ __forceinline__ float4 h4f(uint2 v) {
    const float2 f0 = __half22float2(*(const __half2*)&v.x);
    const float2 f1 = __half22float2(*(const __half2*)&v.y);
    return make_float4(f0.x, f0.y, f1.x, f1.y);
}
__global__ void aggregate(const float* __restrict__ b_gcn, int n) {
    int gw   = (blockIdx.x * blockDim.x + threadIdx.x) >> 5;
    int lane = threadIdx.x & 31;
    if (gw >= n) return;
    const int node = gw;
    const uint2* __restrict__ xg2 = (const uint2*)g_xgh;

    const float4 selfv = h4f(xg2[(size_t)node * 32 + lane]);
    const float  dn    = g_dis[node];
    const int    s0    = g_rowstart[node];
    const int    cnt   = g_deg[node];

    float4 acc = make_float4(0.f, 0.f, 0.f, 0.f);
    int e = s0, eend = s0 + cnt;
    for (; e + 1 < eend; e += 2) {
        const int s1 = g_csr[e], s2 = g_csr[e + 1];
        const float w1 = g_dis[s1], w2 = g_dis[s2];
        const float4 v1 = h4f(xg2[(size_t)s1 * 32 + lane]);
        const float4 v2 = h4f(xg2[(size_t)s2 * 32 + lane]);
        acc.x += v1.x * w1 + v2.x * w2;
        acc.y += v1.y * w1 + v2.y * w2;
        acc.z += v1.z * w1 + v2.z * w2;
        acc.w += v1.w * w1 + v2.w * w2;
    }
    if (e < eend) {
        const int s1 = g_csr[e];
        const float w1 = g_dis[s1];
        const float4 v1 = h4f(xg2[(size_t)s1 * 32 + lane]);
        acc.x += v1.x * w1; acc.y += v1.y * w1;
        acc.z += v1.z * w1; acc.w += v1.w * w1;
    }
    const float sw = dn * dn;
    const float4 b = ((const float4*)b_gcn)[lane];
    float4 o;
    o.x = fmaxf(acc.x * dn + selfv.x * sw + b.x, 0.f);
    o.y = fmaxf(acc.y * dn + selfv.y * sw + b.y, 0.f);
    o.z = fmaxf(acc.z * dn + selfv.z * sw + b.z, 0.f);
    o.w = fmaxf(acc.w * dn + selfv.w * sw + b.w, 0.f);
    const __half2 h0 = __floats2half2_rn(o.x, o.y);
    const __half2 h1 = __floats2half2_rn(o.z, o.w);
    uint32_t* drow = g_diffh + (size_t)node * 64;
    drow[permw(2 * lane)]     = *(const uint32_t*)&h0;
    drow[permw(2 * lane + 1)] = *(const uint32_t*)&h1;
}

// ---------------- launcher --------------------------------------------------------
extern "C" void kernel_launch(void* const* d_in, const int* in_sizes, int n_in,
                              void* d_out, int out_size)
{
    const float* base   = (const float*)d_in[0];
    const float* ev     = (const float*)d_in[1];
    const void*  ei     = d_in[2];
    const float* W_proj = (const float*)d_in[3];
    const float* b_proj = (const float*)d_in[4];
    const float* W_gcn  = (const float*)d_in[5];
    const float* b_gcn  = (const float*)d_in[6];
    const float* W_gate = (const float*)d_in[7];
    const float* b_gate = (const float*)d_in[8];
    const float* W_fuse = (const float*)d_in[9];
    const float* b_fuse = (const float*)d_in[10];

    const int N = in_sizes[0] / HID;
    const int E = in_sizes[2] / 2;

    uint32_t *p_xgh, *p_diffh, *p_evh, *p_baseh;
    __half *p_wtp, *p_wtg, *p_wtga, *p_wtf;
    int *p_deg;
    cudaGetSymbolAddress((void**)&p_xgh,   g_xgh);
    cudaGetSymbolAddress((void**)&p_diffh, g_diffh);
    cudaGetSymbolAddress((void**)&p_evh,   g_evh);
    cudaGetSymbolAddress((void**)&p_baseh, g_baseh);
    cudaGetSymbolAddress((void**)&p_wtp,   g_wt_proj);
    cudaGetSymbolAddress((void**)&p_wtg,   g_wt_gcn);
    cudaGetSymbolAddress((void**)&p_wtga,  g_wt_gate);
    cudaGetSymbolAddress((void**)&p_wtf,   g_wt_fuse);
    cudaGetSymbolAddress((void**)&p_deg,   g_deg);

    cudaFuncSetAttribute(k_proj_gcn,  cudaFuncAttributeMaxDynamicSharedMemorySize, PG_SMEM_W * 4);
    cudaFuncSetAttribute(k_gate_fuse, cudaFuncAttributeMaxDynamicSharedMemorySize, GF_SMEM_W * 4);

    const int gT = (N + 127) / 128;
    const int gE = (E + 255) / 256;
    const int nb = (N + 511) / 512;

    // single side stream for CSR chain + base convert (destroyed before return)
    cudaStream_t side;
    cudaEvent_t evFork, evJoin, evJoin2;
    cudaStreamCreateWithFlags(&side, cudaStreamNonBlocking);
    cudaEventCreateWithFlags(&evFork,  cudaEventDisableTiming);
    cudaEventCreateWithFlags(&evJoin,  cudaEventDisableTiming);
    cudaEventCreateWithFlags(&evJoin2, cudaEventDisableTiming);

    cudaEventRecord(evFork, 0);
    cudaStreamWaitEvent(side, evFork, 0);

    // --- side: CSR build, then base convert (joined separately)
    cudaMemsetAsync(p_deg, 0, (size_t)N * sizeof(int), side);
    count_deg<<<gE, 256, 0, side>>>(ei, E);
    scan1<<<nb, 512, 0, side>>>(N);
    scan2<<<1, 1024, 0, side>>>(nb);
    scan3<<<nb, 512, 0, side>>>(N);
    fill_csr<<<gE, 256, 0, side>>>(ei, E);
    cudaEventRecord(evJoin, side);                      // CSR ready
    cvt_half<64><<<(N * 64 + 255) / 256, 256, 0, side>>>((const float2*)base, p_baseh, N * 64);
    cudaEventRecord(evJoin2, side);                     // baseh ready

    // --- main: weight prep + ev convert + fused proj/gcn GEMM (overlaps side)
    wprep<<<88, 256>>>(W_proj, W_gcn, W_gate, W_fuse, p_wtp, p_wtg, p_wtga, p_wtf);
    cvt_half<32><<<(N * 32 + 255) / 256, 256>>>((const float2*)ev, p_evh, N * 32);
    k_proj_gcn<<<gT, 256, PG_SMEM_W * 4>>>(p_evh, p_wtp, b_proj, p_wtg, p_xgh, N);

    // aggregate needs xgh (main) + CSR (side); overlaps cvt_base on the side stream
    cudaStreamWaitEvent(0, evJoin, 0);
    aggregate<<<(N * 32 + 255) / 256, 256>>>(b_gcn, N);

    // gate_fuse additionally needs baseh
    cudaStreamWaitEvent(0, evJoin2, 0);
    k_gate_fuse<<<gT, 256, GF_SMEM_W * 4>>>(p_baseh, p_diffh, p_wtga, b_gate,
                                            p_wtf, b_fuse, (float*)d_out, N);

    // release resources created this call (graph retains captured dependencies)
    cudaEventDestroy(evFork);
    cudaEventDestroy(evJoin);
    cudaEventDestroy(evJoin2);
    cudaStreamDestroy(side);
}